// round 7
// baseline (speedup 1.0000x reference)
#include <cuda_runtime.h>
#include <cstdint>

// Problem constants (fixed by setup_inputs: P=64, K=8, C=512, N=3*P*K=1536)
#define NROWS 1536
#define CDIM  512
#define MROWS 192      // 3*P
#define KINST 8        // NROWS / MROWS
#define KK    1024     // 2*CDIM  (packed [logx | xs] / [hcen | logh])
#define LOG_EPS -20.72326583694641f  // log(1e-9)
#define MARGIN 6.0f

// GEMM tiling (tf32 mma.sync m16n8k8)
#define KSPLIT 8
#define KCHUNK (KK / KSPLIT)   // 128 k per block
#define GBM 64
#define GBN 64
#define GBK 16                 // k per smem stage (2 k8 sub-steps)
#define NSTG (KCHUNK / GBK)    // 8
#define SPAD 4
#define SSTRIDE (GBK + SPAD)   // 20 words: conflict-free frag LDS, f4-aligned stores

// Scratch (device globals; no allocations allowed)
__device__ float g_A[NROWS * KK];            // [logx | xs]  (tf32-rounded)
__device__ float g_B[MROWS * KK];            // [hcen | logh] (tf32-rounded)
__device__ float g_C[KSPLIT][NROWS * MROWS]; // split-K partial dot products
__device__ float g_entx[NROWS];
__device__ float g_enth[MROWS];
__device__ int   g_pidi[NROWS];
__device__ int   g_pidhc[MROWS];
__device__ float g_acc[4];                   // s1, s2, pos_cnt, neg_cnt
__device__ unsigned g_done;                  // reduce completion counter

__device__ __forceinline__ float to_tf32(float x) {
    uint32_t r;
    asm("cvt.rna.tf32.f32 %0, %1;" : "=r"(r) : "f"(x));
    return __uint_as_float(r);
}

// ---------------------------------------------------------------------------
// Kernel 1: row softmax -> logx (clipped) and xs into packed A (tf32), ent_x.
// Block 0 additionally does prep: zero accumulators, detect pids element
// width (int32 vs int64), extract per-row / per-cluster pids. (Those outputs
// are consumed only by the reduce kernel, launched later.)
// ---------------------------------------------------------------------------
__global__ __launch_bounds__(256) void softmax_kernel(const float* __restrict__ x,
                                                      const int* __restrict__ pw) {
    int tid = threadIdx.x;
    if (blockIdx.x == 0) {
        if (tid < 4) g_acc[tid] = 0.0f;
        if (tid == 0) g_done = 0u;
        int q = 1 + 2 * tid;               // odd words 1..511 (safe for both widths)
        int nz = (pw[q] != 0) ? 1 : 0;
        int any = __syncthreads_or(nz);    // int64 LE small values -> odd words all 0
        int stride = any ? 1 : 2;
        for (int i = tid; i < NROWS; i += 256) g_pidi[i]  = pw[i * stride];
        for (int j = tid; j < MROWS; j += 256) g_pidhc[j] = pw[j * KINST * stride];
    }

    int warp = tid >> 5;
    int lane = tid & 31;
    int row = blockIdx.x * 8 + warp;
    const float* xr = x + (size_t)row * CDIM;
    float v[16];
    float mx = -1e30f;
#pragma unroll
    for (int t = 0; t < 16; t++) {
        v[t] = xr[t * 32 + lane];
        mx = fmaxf(mx, v[t]);
    }
#pragma unroll
    for (int o = 16; o > 0; o >>= 1) mx = fmaxf(mx, __shfl_xor_sync(0xffffffffu, mx, o));
    float e[16];
    float s = 0.f;
#pragma unroll
    for (int t = 0; t < 16; t++) { e[t] = __expf(v[t] - mx); s += e[t]; }
#pragma unroll
    for (int o = 16; o > 0; o >>= 1) s += __shfl_xor_sync(0xffffffffu, s, o);
    float ls = __logf(s);
    float inv = 1.0f / s;
    float ent = 0.f;
    float* Ar = g_A + (size_t)row * KK;
#pragma unroll
    for (int t = 0; t < 16; t++) {
        float lx = fmaxf(v[t] - mx - ls, LOG_EPS);
        float xs = e[t] * inv;
        Ar[t * 32 + lane]        = to_tf32(lx);
        Ar[CDIM + t * 32 + lane] = to_tf32(xs);
        ent += xs * lx;
    }
#pragma unroll
    for (int o = 16; o > 0; o >>= 1) ent += __shfl_xor_sync(0xffffffffu, ent, o);
    if (lane == 0) g_entx[row] = ent;
}

// ---------------------------------------------------------------------------
// Kernel 2: cluster centers (mean of KINST rows of xs), logh, ent_h.
// ---------------------------------------------------------------------------
__global__ __launch_bounds__(256) void center_kernel() {
    int j = blockIdx.x;
    int tid = threadIdx.x;
    __shared__ float sred[256];
    float entp = 0.f;
    float* Bj = g_B + (size_t)j * KK;
    for (int c = tid; c < CDIM; c += 256) {
        float s = 0.f;
#pragma unroll
        for (int r = 0; r < KINST; r++)
            s += g_A[(size_t)(j * KINST + r) * KK + CDIM + c];
        float h = s * (1.0f / KINST);
        float lh = __logf(fmaxf(h, 1e-9f));
        Bj[c]        = to_tf32(h);
        Bj[CDIM + c] = to_tf32(lh);
        entp += h * lh;
    }
    sred[tid] = entp;
    __syncthreads();
    for (int o = 128; o > 0; o >>= 1) {
        if (tid < o) sred[tid] += sred[tid + o];
        __syncthreads();
    }
    if (tid == 0) g_enth[j] = sred[0];
}

// ---------------------------------------------------------------------------
// Kernel 3: tf32 tensor-core GEMM, split-K=8, partials to g_C[z].
// 128 threads = 4 warps (2x2), warp tile 32x32 = 2x4 m16n8k8 mma tiles.
// Grid (24,3,8) = 576 blocks -> ~4 blocks/SM for latency hiding.
// ---------------------------------------------------------------------------
__global__ __launch_bounds__(128) void mma_kernel() {
    __shared__ float As[2][GBM][SSTRIDE];
    __shared__ float Bs[2][GBN][SSTRIDE];
    const int tid = threadIdx.x;
    const int lane = tid & 31;
    const int wid = tid >> 5;
    const int wm = wid & 1, wn = wid >> 1;
    const int i0 = blockIdx.x * GBM;
    const int j0 = blockIdx.y * GBN;
    const float* Ag = g_A + (size_t)i0 * KK + blockIdx.z * KCHUNK;
    const float* Bg = g_B + (size_t)j0 * KK + blockIdx.z * KCHUNK;

    const int lrow0 = tid >> 2;             // 0..31
    const int lrow1 = lrow0 + 32;           // 32..63
    const int lkc   = (tid & 3) * 4;        // 0,4,8,12

    float c[2][4][4] = {};
    float4 va0, va1, vb0, vb1;

    va0 = *(const float4*)(Ag + (size_t)lrow0 * KK + lkc);
    va1 = *(const float4*)(Ag + (size_t)lrow1 * KK + lkc);
    vb0 = *(const float4*)(Bg + (size_t)lrow0 * KK + lkc);
    vb1 = *(const float4*)(Bg + (size_t)lrow1 * KK + lkc);
    *(float4*)&As[0][lrow0][lkc] = va0;
    *(float4*)&As[0][lrow1][lkc] = va1;
    *(float4*)&Bs[0][lrow0][lkc] = vb0;
    *(float4*)&Bs[0][lrow1][lkc] = vb1;
    __syncthreads();

    const int fr = lane >> 2;   // fragment row/col
    const int fk = lane & 3;    // fragment k

    for (int st = 0; st < NSTG; st++) {
        const int buf = st & 1;
        if (st + 1 < NSTG) {
            int ck = (st + 1) * GBK;
            va0 = *(const float4*)(Ag + (size_t)lrow0 * KK + lkc + ck);
            va1 = *(const float4*)(Ag + (size_t)lrow1 * KK + lkc + ck);
            vb0 = *(const float4*)(Bg + (size_t)lrow0 * KK + lkc + ck);
            vb1 = *(const float4*)(Bg + (size_t)lrow1 * KK + lkc + ck);
        }
#pragma unroll
        for (int ks = 0; ks < 2; ks++) {
            const int k0 = ks * 8 + fk;
            uint32_t a[2][4], b[4][2];
#pragma unroll
            for (int mi = 0; mi < 2; mi++) {
                int r0 = wm * 32 + mi * 16 + fr;
                a[mi][0] = __float_as_uint(As[buf][r0][k0]);
                a[mi][1] = __float_as_uint(As[buf][r0 + 8][k0]);
                a[mi][2] = __float_as_uint(As[buf][r0][k0 + 4]);
                a[mi][3] = __float_as_uint(As[buf][r0 + 8][k0 + 4]);
            }
#pragma unroll
            for (int ni = 0; ni < 4; ni++) {
                int c0 = wn * 32 + ni * 8 + fr;
                b[ni][0] = __float_as_uint(Bs[buf][c0][k0]);
                b[ni][1] = __float_as_uint(Bs[buf][c0][k0 + 4]);
            }
#pragma unroll
            for (int mi = 0; mi < 2; mi++)
#pragma unroll
                for (int ni = 0; ni < 4; ni++)
                    asm volatile(
                        "mma.sync.aligned.m16n8k8.row.col.f32.tf32.tf32.f32 "
                        "{%0,%1,%2,%3}, {%4,%5,%6,%7}, {%8,%9}, {%0,%1,%2,%3};\n"
                        : "+f"(c[mi][ni][0]), "+f"(c[mi][ni][1]),
                          "+f"(c[mi][ni][2]), "+f"(c[mi][ni][3])
                        : "r"(a[mi][0]), "r"(a[mi][1]), "r"(a[mi][2]), "r"(a[mi][3]),
                          "r"(b[ni][0]), "r"(b[ni][1]));
        }
        if (st + 1 < NSTG) {
            __syncthreads();
            const int nb = buf ^ 1;
            *(float4*)&As[nb][lrow0][lkc] = va0;
            *(float4*)&As[nb][lrow1][lkc] = va1;
            *(float4*)&Bs[nb][lrow0][lkc] = vb0;
            *(float4*)&Bs[nb][lrow1][lkc] = vb1;
            __syncthreads();
        }
    }

    float* Cz = g_C[blockIdx.z];
#pragma unroll
    for (int mi = 0; mi < 2; mi++) {
        int ib = i0 + wm * 32 + mi * 16 + fr;
#pragma unroll
        for (int ni = 0; ni < 4; ni++) {
            int jj = j0 + wn * 32 + ni * 8 + fk * 2;
            *(float2*)&Cz[(size_t)ib * MROWS + jj]       = make_float2(c[mi][ni][0], c[mi][ni][1]);
            *(float2*)&Cz[(size_t)(ib + 8) * MROWS + jj] = make_float2(c[mi][ni][2], c[mi][ni][3]);
        }
    }
}

// ---------------------------------------------------------------------------
// Kernel 4: reduce split-K partials -> dist -> masked loss accumulators.
// Last block to finish also finalizes the scalar output.
// ---------------------------------------------------------------------------
__global__ __launch_bounds__(192) void reduce_kernel(float* __restrict__ out) {
    const int j = threadIdx.x;
    const float eh = g_enth[j];
    const int ph = g_pidhc[j];
    const bool jl = j < (2 * MROWS / 3);   // 128
    float s1 = 0.f, s2 = 0.f, c1 = 0.f, c2 = 0.f;
    const int i0 = blockIdx.x * 8;
#pragma unroll
    for (int u = 0; u < 8; u++) {
        int i = i0 + u;
        size_t e = (size_t)i * MROWS + j;
        float v = 0.f;
#pragma unroll
        for (int z = 0; z < KSPLIT; z++) v += g_C[z][e];
        float d = g_entx[i] + eh - v;
        bool il = i < (2 * NROWS / 3);     // 1024
        if (g_pidi[i] == ph) {
            if (il != jl) { s1 += d; c1 += 1.f; }
        } else {
            s2 += fmaxf(MARGIN - d, 0.f);
            c2 += 1.f;
        }
    }
#pragma unroll
    for (int o = 16; o > 0; o >>= 1) {
        s1 += __shfl_xor_sync(0xffffffffu, s1, o);
        s2 += __shfl_xor_sync(0xffffffffu, s2, o);
        c1 += __shfl_xor_sync(0xffffffffu, c1, o);
        c2 += __shfl_xor_sync(0xffffffffu, c2, o);
    }
    __shared__ float red[6][4];
    __shared__ bool last;
    int w = j >> 5, ln = j & 31;
    if (ln == 0) { red[w][0] = s1; red[w][1] = s2; red[w][2] = c1; red[w][3] = c2; }
    __syncthreads();
    if (j < 4) {
        float v = 0.f;
#pragma unroll
        for (int w2 = 0; w2 < 6; w2++) v += red[w2][j];
        atomicAdd(&g_acc[j], v);
    }
    __threadfence();
    if (j == 0) {
        unsigned t = atomicAdd(&g_done, 1u);
        last = (t == (NROWS / 8) - 1);
    }
    __syncthreads();
    if (last && j == 0) {
        volatile float* acc = g_acc;
        out[0] = acc[0] / fmaxf(acc[2], 1.f) + acc[1] / fmaxf(acc[3], 1.f);
    }
}

extern "C" void kernel_launch(void* const* d_in, const int* in_sizes, int n_in,
                              void* d_out, int out_size) {
    const float* x = (const float*)d_in[0];
    const int* pids_words = (const int*)d_in[1];   // width auto-detected on device
    (void)in_sizes; (void)n_in; (void)out_size;

    softmax_kernel<<<NROWS / 8, 256>>>(x, pids_words);
    center_kernel<<<MROWS, 256>>>();
    dim3 grid(NROWS / GBM, MROWS / GBN, KSPLIT);   // (24, 3, 8)
    mma_kernel<<<grid, 128>>>();
    reduce_kernel<<<NROWS / 8, 192>>>((float*)d_out);
}

// round 8
// speedup vs baseline: 1.0094x; 1.0094x over previous
#include <cuda_runtime.h>
#include <cstdint>

// Problem constants (fixed by setup_inputs: P=64, K=8, C=512, N=3*P*K=1536)
#define NROWS 1536
#define CDIM  512
#define MROWS 192      // 3*P
#define KINST 8        // NROWS / MROWS
#define KK    1024     // 2*CDIM  (packed [logx | xs] / [hcen | logh])
#define LOG_EPS -20.72326583694641f  // log(1e-9)
#define MARGIN 6.0f

// GEMM tiling (tf32 mma.sync m16n8k8)
#define KSPLIT 8
#define KCHUNK (KK / KSPLIT)   // 128 k per block
#define GBM 64
#define GBN 64
#define GBK 16                 // k per smem stage (2 k8 sub-steps)
#define NSTG (KCHUNK / GBK)    // 8
#define SPAD 4
#define SSTRIDE (GBK + SPAD)   // 20 words: conflict-free frag LDS, f4-aligned stores
#define NTILES ((NROWS / GBM) * (MROWS / GBN))   // 24*3 = 72

// Scratch (device globals; no allocations allowed)
__device__ float g_A[NROWS * KK];            // [logx | xs]  (tf32-rounded)
__device__ float g_B[MROWS * KK];            // [hcen | logh] (tf32-rounded)
__device__ float g_C[KSPLIT][NROWS * MROWS]; // split-K partial dot products
__device__ float g_entx[NROWS];
__device__ float g_enth[MROWS];
__device__ int   g_pidi[NROWS];
__device__ int   g_pidhc[MROWS];
__device__ float g_acc[4];                   // s1, s2, pos_cnt, neg_cnt
__device__ unsigned g_tile[NTILES];          // per-tile z-arrival counters
__device__ unsigned g_done;                  // finished-tile counter

__device__ __forceinline__ float to_tf32(float x) {
    uint32_t r;
    asm("cvt.rna.tf32.f32 %0, %1;" : "=r"(r) : "f"(x));
    return __uint_as_float(r);
}

// ---------------------------------------------------------------------------
// Kernel 1: row softmax -> logx (clipped) and xs into packed A (tf32), ent_x.
// Block 0 additionally: zero accumulators/counters, detect pids element width
// (int32 vs int64), extract per-row / per-cluster pids.
// ---------------------------------------------------------------------------
__global__ __launch_bounds__(256) void softmax_kernel(const float* __restrict__ x,
                                                      const int* __restrict__ pw) {
    int tid = threadIdx.x;
    if (blockIdx.x == 0) {
        if (tid < 4) g_acc[tid] = 0.0f;
        if (tid == 0) g_done = 0u;
        if (tid < NTILES) g_tile[tid] = 0u;
        int q = 1 + 2 * tid;               // odd words 1..511 (safe for both widths)
        int nz = (pw[q] != 0) ? 1 : 0;
        int any = __syncthreads_or(nz);    // int64 LE small values -> odd words all 0
        int stride = any ? 1 : 2;
        for (int i = tid; i < NROWS; i += 256) g_pidi[i]  = pw[i * stride];
        for (int j = tid; j < MROWS; j += 256) g_pidhc[j] = pw[j * KINST * stride];
    }

    int warp = tid >> 5;
    int lane = tid & 31;
    int row = blockIdx.x * 8 + warp;
    const float* xr = x + (size_t)row * CDIM;
    float v[16];
    float mx = -1e30f;
#pragma unroll
    for (int t = 0; t < 16; t++) {
        v[t] = xr[t * 32 + lane];
        mx = fmaxf(mx, v[t]);
    }
#pragma unroll
    for (int o = 16; o > 0; o >>= 1) mx = fmaxf(mx, __shfl_xor_sync(0xffffffffu, mx, o));
    float e[16];
    float s = 0.f;
#pragma unroll
    for (int t = 0; t < 16; t++) { e[t] = __expf(v[t] - mx); s += e[t]; }
#pragma unroll
    for (int o = 16; o > 0; o >>= 1) s += __shfl_xor_sync(0xffffffffu, s, o);
    float ls = __logf(s);
    float inv = 1.0f / s;
    float ent = 0.f;
    float* Ar = g_A + (size_t)row * KK;
#pragma unroll
    for (int t = 0; t < 16; t++) {
        float lx = fmaxf(v[t] - mx - ls, LOG_EPS);
        float xs = e[t] * inv;
        Ar[t * 32 + lane]        = to_tf32(lx);
        Ar[CDIM + t * 32 + lane] = to_tf32(xs);
        ent += xs * lx;
    }
#pragma unroll
    for (int o = 16; o > 0; o >>= 1) ent += __shfl_xor_sync(0xffffffffu, ent, o);
    if (lane == 0) g_entx[row] = ent;
}

// ---------------------------------------------------------------------------
// Kernel 2: cluster centers (mean of KINST rows of xs), logh, ent_h.
// ---------------------------------------------------------------------------
__global__ __launch_bounds__(256) void center_kernel() {
    int j = blockIdx.x;
    int tid = threadIdx.x;
    __shared__ float sred[256];
    float entp = 0.f;
    float* Bj = g_B + (size_t)j * KK;
    for (int c = tid; c < CDIM; c += 256) {
        float s = 0.f;
#pragma unroll
        for (int r = 0; r < KINST; r++)
            s += g_A[(size_t)(j * KINST + r) * KK + CDIM + c];
        float h = s * (1.0f / KINST);
        float lh = __logf(fmaxf(h, 1e-9f));
        Bj[c]        = to_tf32(h);
        Bj[CDIM + c] = to_tf32(lh);
        entp += h * lh;
    }
    sred[tid] = entp;
    __syncthreads();
    for (int o = 128; o > 0; o >>= 1) {
        if (tid < o) sred[tid] += sred[tid + o];
        __syncthreads();
    }
    if (tid == 0) g_enth[j] = sred[0];
}

// ---------------------------------------------------------------------------
// Kernel 3: tf32 tensor-core GEMM, split-K=8, with fused loss epilogue.
// 128 threads = 4 warps (2x2), warp tile 32x32 = 2x4 m16n8k8 mma tiles.
// Each z-block writes its partial tile; the LAST z-block per (x,y) tile
// (threadfence-reduction pattern) sums the 8 partials, applies the masked
// hinge/positive loss, and atomically accumulates. Last tile writes out.
// ---------------------------------------------------------------------------
__global__ __launch_bounds__(128, 4) void mma_kernel(float* __restrict__ out) {
    __shared__ float As[2][GBM][SSTRIDE];
    __shared__ float Bs[2][GBN][SSTRIDE];
    const int tid = threadIdx.x;
    const int lane = tid & 31;
    const int wid = tid >> 5;
    const int wm = wid & 1, wn = wid >> 1;
    const int i0 = blockIdx.x * GBM;
    const int j0 = blockIdx.y * GBN;
    const float* Ag = g_A + (size_t)i0 * KK + blockIdx.z * KCHUNK;
    const float* Bg = g_B + (size_t)j0 * KK + blockIdx.z * KCHUNK;

    const int lrow0 = tid >> 2;             // 0..31
    const int lrow1 = lrow0 + 32;           // 32..63
    const int lkc   = (tid & 3) * 4;        // 0,4,8,12

    float c[2][4][4] = {};
    float4 va0, va1, vb0, vb1;

    va0 = *(const float4*)(Ag + (size_t)lrow0 * KK + lkc);
    va1 = *(const float4*)(Ag + (size_t)lrow1 * KK + lkc);
    vb0 = *(const float4*)(Bg + (size_t)lrow0 * KK + lkc);
    vb1 = *(const float4*)(Bg + (size_t)lrow1 * KK + lkc);
    *(float4*)&As[0][lrow0][lkc] = va0;
    *(float4*)&As[0][lrow1][lkc] = va1;
    *(float4*)&Bs[0][lrow0][lkc] = vb0;
    *(float4*)&Bs[0][lrow1][lkc] = vb1;
    __syncthreads();

    const int fr = lane >> 2;   // fragment row/col
    const int fk = lane & 3;    // fragment k

    for (int st = 0; st < NSTG; st++) {
        const int buf = st & 1;
        if (st + 1 < NSTG) {
            int ck = (st + 1) * GBK;
            va0 = *(const float4*)(Ag + (size_t)lrow0 * KK + lkc + ck);
            va1 = *(const float4*)(Ag + (size_t)lrow1 * KK + lkc + ck);
            vb0 = *(const float4*)(Bg + (size_t)lrow0 * KK + lkc + ck);
            vb1 = *(const float4*)(Bg + (size_t)lrow1 * KK + lkc + ck);
        }
#pragma unroll
        for (int ks = 0; ks < 2; ks++) {
            const int k0 = ks * 8 + fk;
            uint32_t a[2][4], b[4][2];
#pragma unroll
            for (int mi = 0; mi < 2; mi++) {
                int r0 = wm * 32 + mi * 16 + fr;
                a[mi][0] = __float_as_uint(As[buf][r0][k0]);
                a[mi][1] = __float_as_uint(As[buf][r0 + 8][k0]);
                a[mi][2] = __float_as_uint(As[buf][r0][k0 + 4]);
                a[mi][3] = __float_as_uint(As[buf][r0 + 8][k0 + 4]);
            }
#pragma unroll
            for (int ni = 0; ni < 4; ni++) {
                int c0 = wn * 32 + ni * 8 + fr;
                b[ni][0] = __float_as_uint(Bs[buf][c0][k0]);
                b[ni][1] = __float_as_uint(Bs[buf][c0][k0 + 4]);
            }
#pragma unroll
            for (int mi = 0; mi < 2; mi++)
#pragma unroll
                for (int ni = 0; ni < 4; ni++)
                    asm volatile(
                        "mma.sync.aligned.m16n8k8.row.col.f32.tf32.tf32.f32 "
                        "{%0,%1,%2,%3}, {%4,%5,%6,%7}, {%8,%9}, {%0,%1,%2,%3};\n"
                        : "+f"(c[mi][ni][0]), "+f"(c[mi][ni][1]),
                          "+f"(c[mi][ni][2]), "+f"(c[mi][ni][3])
                        : "r"(a[mi][0]), "r"(a[mi][1]), "r"(a[mi][2]), "r"(a[mi][3]),
                          "r"(b[ni][0]), "r"(b[ni][1]));
        }
        if (st + 1 < NSTG) {
            __syncthreads();
            const int nb = buf ^ 1;
            *(float4*)&As[nb][lrow0][lkc] = va0;
            *(float4*)&As[nb][lrow1][lkc] = va1;
            *(float4*)&Bs[nb][lrow0][lkc] = vb0;
            *(float4*)&Bs[nb][lrow1][lkc] = vb1;
            __syncthreads();
        }
    }

    // Write this z-slice's partial tile
    float* Cz = g_C[blockIdx.z];
#pragma unroll
    for (int mi = 0; mi < 2; mi++) {
        int ib = i0 + wm * 32 + mi * 16 + fr;
#pragma unroll
        for (int ni = 0; ni < 4; ni++) {
            int jj = j0 + wn * 32 + ni * 8 + fk * 2;
            *(float2*)&Cz[(size_t)ib * MROWS + jj]       = make_float2(c[mi][ni][0], c[mi][ni][1]);
            *(float2*)&Cz[(size_t)(ib + 8) * MROWS + jj] = make_float2(c[mi][ni][2], c[mi][ni][3]);
        }
    }

    // Threadfence-reduction: last z-block for this tile does the loss epilogue.
    __threadfence();
    __syncthreads();
    __shared__ bool lastz;
    const int tile = blockIdx.y * (NROWS / GBM) + blockIdx.x;
    if (tid == 0) lastz = (atomicAdd(&g_tile[tile], 1u) == KSPLIT - 1);
    __syncthreads();
    if (!lastz) return;

    const int jj = tid & 63;                // tile column
    const int ih = tid >> 6;                // row half (0/1)
    const int jcol = j0 + jj;
    const float eh = g_enth[jcol];
    const int ph = g_pidhc[jcol];
    const bool jl = jcol < (2 * MROWS / 3); // 128
    float s1 = 0.f, s2 = 0.f, c1 = 0.f, c2 = 0.f;
#pragma unroll 4
    for (int u = 0; u < 32; u++) {
        int i = i0 + ih * 32 + u;
        size_t e = (size_t)i * MROWS + jcol;
        float v = 0.f;
#pragma unroll
        for (int z = 0; z < KSPLIT; z++) v += g_C[z][e];
        float d = g_entx[i] + eh - v;
        bool il = i < (2 * NROWS / 3);      // 1024
        if (g_pidi[i] == ph) {
            if (il != jl) { s1 += d; c1 += 1.f; }
        } else {
            s2 += fmaxf(MARGIN - d, 0.f);
            c2 += 1.f;
        }
    }
#pragma unroll
    for (int o = 16; o > 0; o >>= 1) {
        s1 += __shfl_xor_sync(0xffffffffu, s1, o);
        s2 += __shfl_xor_sync(0xffffffffu, s2, o);
        c1 += __shfl_xor_sync(0xffffffffu, c1, o);
        c2 += __shfl_xor_sync(0xffffffffu, c2, o);
    }
    __shared__ float red[4][4];
    __shared__ bool lastall;
    if (lane == 0) { red[wid][0] = s1; red[wid][1] = s2; red[wid][2] = c1; red[wid][3] = c2; }
    __syncthreads();
    if (tid < 4) {
        float v = red[0][tid] + red[1][tid] + red[2][tid] + red[3][tid];
        atomicAdd(&g_acc[tid], v);
    }
    __threadfence();
    if (tid == 0) lastall = (atomicAdd(&g_done, 1u) == NTILES - 1);
    __syncthreads();
    if (lastall && tid == 0) {
        volatile float* acc = g_acc;
        out[0] = acc[0] / fmaxf(acc[2], 1.f) + acc[1] / fmaxf(acc[3], 1.f);
    }
}

extern "C" void kernel_launch(void* const* d_in, const int* in_sizes, int n_in,
                              void* d_out, int out_size) {
    const float* x = (const float*)d_in[0];
    const int* pids_words = (const int*)d_in[1];   // width auto-detected on device
    (void)in_sizes; (void)n_in; (void)out_size;

    softmax_kernel<<<NROWS / 8, 256>>>(x, pids_words);
    center_kernel<<<MROWS, 256>>>();
    dim3 grid(NROWS / GBM, MROWS / GBN, KSPLIT);   // (24, 3, 8)
    mma_kernel<<<grid, 128>>>((float*)d_out);
}

// round 11
// speedup vs baseline: 1.0673x; 1.0574x over previous
#include <cuda_runtime.h>
#include <cstdint>

// Problem constants (fixed by setup_inputs: P=64, K=8, C=512, N=3*P*K=1536)
#define NROWS 1536
#define CDIM  512
#define MROWS 192      // 3*P
#define KINST 8        // NROWS / MROWS
#define KK    1024     // 2*CDIM  (packed [logx | xs] / [hcen | logh])
#define LOG_EPS -20.72326583694641f  // log(1e-9)
#define MARGIN 6.0f

// GEMM tiling (tf32 mma.sync m16n8k8)
#define KSPLIT 8
#define KCHUNK (KK / KSPLIT)   // 128 k per block
#define GBM 64
#define GBN 64
#define GBK 16                 // k per smem stage (2 k8 sub-steps)
#define NSTG (KCHUNK / GBK)    // 8
#define SPAD 4
#define SSTRIDE (GBK + SPAD)   // 20 words: conflict-free frag LDS, f4-aligned stores
#define NTILES ((NROWS / GBM) * (MROWS / GBN))   // 24*3 = 72

// Scratch (device globals; no allocations allowed)
__device__ float g_A[NROWS * KK];            // [logx | xs]  (tf32-rounded)
__device__ float g_B[MROWS * KK];            // [hcen | logh] (tf32-rounded)
__device__ float g_C[KSPLIT][NROWS * MROWS]; // split-K partial dot products
__device__ float g_entx[NROWS];
__device__ float g_enth[MROWS];
__device__ int   g_pidi[NROWS];
__device__ int   g_pidhc[MROWS];
__device__ float g_acc[4];                   // s1, s2, pos_cnt, neg_cnt
__device__ unsigned g_tile[NTILES];          // per-tile z-arrival counters
__device__ unsigned g_done;                  // finished-tile counter

__device__ __forceinline__ float to_tf32(float x) {
    uint32_t r;
    asm("cvt.rna.tf32.f32 %0, %1;" : "=r"(r) : "f"(x));
    return __uint_as_float(r);
}

// ---------------------------------------------------------------------------
// Kernel 1 (fused): softmax + cluster centers.
// Block b (256 thr, 8 warps) owns rows [8b, 8b+8) == exactly cluster b.
//  - warp w: softmax of row 8b+w (float4 I/O), writes logx|xs to g_A, ent_x;
//    stages xs into smem.
//  - after barrier: 256 threads compute the cluster mean/log/entropy over the
//    8 staged rows and write g_B (hcen|logh) + g_enth.
// Block 0 additionally: zero accumulators/counters, detect pids element width
// (int32 vs int64), extract per-row / per-cluster pids.
// ---------------------------------------------------------------------------
__global__ __launch_bounds__(256) void softmax_center_kernel(const float* __restrict__ x,
                                                             const int* __restrict__ pw) {
    __shared__ float sxs[KINST * CDIM];       // 16 KB staged xs
    __shared__ float sred[256];
    int tid = threadIdx.x;
    if (blockIdx.x == 0) {
        if (tid < 4) g_acc[tid] = 0.0f;
        if (tid == 0) g_done = 0u;
        if (tid < NTILES) g_tile[tid] = 0u;
        int q = 1 + 2 * tid;               // odd words 1..511 (safe for both widths)
        int nz = (pw[q] != 0) ? 1 : 0;
        int any = __syncthreads_or(nz);    // int64 LE small values -> odd words all 0
        int stride = any ? 1 : 2;
        for (int i = tid; i < NROWS; i += 256) g_pidi[i]  = pw[i * stride];
        for (int j = tid; j < MROWS; j += 256) g_pidhc[j] = pw[j * KINST * stride];
    }

    const int warp = tid >> 5;
    const int lane = tid & 31;
    const int row = blockIdx.x * KINST + warp;
    const float4* xr4 = (const float4*)(x + (size_t)row * CDIM);

    float4 v4[4];
    float mx = -1e30f;
#pragma unroll
    for (int q = 0; q < 4; q++) {
        v4[q] = xr4[lane + 32 * q];
        mx = fmaxf(mx, fmaxf(fmaxf(v4[q].x, v4[q].y), fmaxf(v4[q].z, v4[q].w)));
    }
#pragma unroll
    for (int o = 16; o > 0; o >>= 1) mx = fmaxf(mx, __shfl_xor_sync(0xffffffffu, mx, o));

    float e[16];
    float s = 0.f;
#pragma unroll
    for (int q = 0; q < 4; q++) {
        const float* vv = (const float*)&v4[q];
#pragma unroll
        for (int u = 0; u < 4; u++) { e[q * 4 + u] = __expf(vv[u] - mx); s += e[q * 4 + u]; }
    }
#pragma unroll
    for (int o = 16; o > 0; o >>= 1) s += __shfl_xor_sync(0xffffffffu, s, o);
    float ls = __logf(s);
    float inv = 1.0f / s;
    float ent = 0.f;

    float4* Ar4  = (float4*)(g_A + (size_t)row * KK);          // logx at [0,512)
    float4* Axs4 = Ar4 + CDIM / 4;                             // xs   at [512,1024)
    float4* sw4  = (float4*)(sxs + warp * CDIM);
#pragma unroll
    for (int q = 0; q < 4; q++) {
        const float* vv = (const float*)&v4[q];
        float4 lx4, xs4;
        float* lxp = (float*)&lx4; float* xsp = (float*)&xs4;
#pragma unroll
        for (int u = 0; u < 4; u++) {
            float lx = fmaxf(vv[u] - mx - ls, LOG_EPS);
            float xs = e[q * 4 + u] * inv;
            lxp[u] = to_tf32(lx);
            xsp[u] = to_tf32(xs);
            ent += xs * lx;
        }
        Ar4[lane + 32 * q]  = lx4;
        Axs4[lane + 32 * q] = xs4;
        sw4[lane + 32 * q]  = xs4;          // stage xs for the center pass
    }
#pragma unroll
    for (int o = 16; o > 0; o >>= 1) ent += __shfl_xor_sync(0xffffffffu, ent, o);
    if (lane == 0) g_entx[row] = ent;
    __syncthreads();

    // Center pass: this block IS cluster j = blockIdx.x. 2 columns per thread.
    const int j = blockIdx.x;
    float* Bj = g_B + (size_t)j * KK;
    float entp = 0.f;
#pragma unroll
    for (int t = 0; t < 2; t++) {
        int c = tid + t * 256;
        float hsum = 0.f;
#pragma unroll
        for (int r = 0; r < KINST; r++) hsum += sxs[r * CDIM + c];
        float h = hsum * (1.0f / KINST);
        float lh = __logf(fmaxf(h, 1e-9f));
        Bj[c]        = to_tf32(h);
        Bj[CDIM + c] = to_tf32(lh);
        entp += h * lh;
    }
    sred[tid] = entp;
    __syncthreads();
    for (int o = 128; o > 0; o >>= 1) {
        if (tid < o) sred[tid] += sred[tid + o];
        __syncthreads();
    }
    if (tid == 0) g_enth[j] = sred[0];
}

// ---------------------------------------------------------------------------
// Kernel 2: tf32 tensor-core GEMM, split-K=8, with fused loss epilogue.
// (byte-identical mainloop to R8's passing version)
// ---------------------------------------------------------------------------
__global__ __launch_bounds__(128, 4) void mma_kernel(float* __restrict__ out) {
    __shared__ float As[2][GBM][SSTRIDE];
    __shared__ float Bs[2][GBN][SSTRIDE];
    const int tid = threadIdx.x;
    const int lane = tid & 31;
    const int wid = tid >> 5;
    const int wm = wid & 1, wn = wid >> 1;
    const int i0 = blockIdx.x * GBM;
    const int j0 = blockIdx.y * GBN;
    const float* Ag = g_A + (size_t)i0 * KK + blockIdx.z * KCHUNK;
    const float* Bg = g_B + (size_t)j0 * KK + blockIdx.z * KCHUNK;

    const int lrow0 = tid >> 2;             // 0..31
    const int lrow1 = lrow0 + 32;           // 32..63
    const int lkc   = (tid & 3) * 4;        // 0,4,8,12

    float c[2][4][4] = {};
    float4 va0, va1, vb0, vb1;

    va0 = *(const float4*)(Ag + (size_t)lrow0 * KK + lkc);
    va1 = *(const float4*)(Ag + (size_t)lrow1 * KK + lkc);
    vb0 = *(const float4*)(Bg + (size_t)lrow0 * KK + lkc);
    vb1 = *(const float4*)(Bg + (size_t)lrow1 * KK + lkc);
    *(float4*)&As[0][lrow0][lkc] = va0;
    *(float4*)&As[0][lrow1][lkc] = va1;
    *(float4*)&Bs[0][lrow0][lkc] = vb0;
    *(float4*)&Bs[0][lrow1][lkc] = vb1;
    __syncthreads();

    const int fr = lane >> 2;   // fragment row/col
    const int fk = lane & 3;    // fragment k

    for (int st = 0; st < NSTG; st++) {
        const int buf = st & 1;
        if (st + 1 < NSTG) {
            int ck = (st + 1) * GBK;
            va0 = *(const float4*)(Ag + (size_t)lrow0 * KK + lkc + ck);
            va1 = *(const float4*)(Ag + (size_t)lrow1 * KK + lkc + ck);
            vb0 = *(const float4*)(Bg + (size_t)lrow0 * KK + lkc + ck);
            vb1 = *(const float4*)(Bg + (size_t)lrow1 * KK + lkc + ck);
        }
#pragma unroll
        for (int ks = 0; ks < 2; ks++) {
            const int k0 = ks * 8 + fk;
            uint32_t a[2][4], b[4][2];
#pragma unroll
            for (int mi = 0; mi < 2; mi++) {
                int r0 = wm * 32 + mi * 16 + fr;
                a[mi][0] = __float_as_uint(As[buf][r0][k0]);
                a[mi][1] = __float_as_uint(As[buf][r0 + 8][k0]);
                a[mi][2] = __float_as_uint(As[buf][r0][k0 + 4]);
                a[mi][3] = __float_as_uint(As[buf][r0 + 8][k0 + 4]);
            }
#pragma unroll
            for (int ni = 0; ni < 4; ni++) {
                int c0 = wn * 32 + ni * 8 + fr;
                b[ni][0] = __float_as_uint(Bs[buf][c0][k0]);
                b[ni][1] = __float_as_uint(Bs[buf][c0][k0 + 4]);
            }
#pragma unroll
            for (int mi = 0; mi < 2; mi++)
#pragma unroll
                for (int ni = 0; ni < 4; ni++)
                    asm volatile(
                        "mma.sync.aligned.m16n8k8.row.col.f32.tf32.tf32.f32 "
                        "{%0,%1,%2,%3}, {%4,%5,%6,%7}, {%8,%9}, {%0,%1,%2,%3};\n"
                        : "+f"(c[mi][ni][0]), "+f"(c[mi][ni][1]),
                          "+f"(c[mi][ni][2]), "+f"(c[mi][ni][3])
                        : "r"(a[mi][0]), "r"(a[mi][1]), "r"(a[mi][2]), "r"(a[mi][3]),
                          "r"(b[ni][0]), "r"(b[ni][1]));
        }
        if (st + 1 < NSTG) {
            __syncthreads();
            const int nb = buf ^ 1;
            *(float4*)&As[nb][lrow0][lkc] = va0;
            *(float4*)&As[nb][lrow1][lkc] = va1;
            *(float4*)&Bs[nb][lrow0][lkc] = vb0;
            *(float4*)&Bs[nb][lrow1][lkc] = vb1;
            __syncthreads();
        }
    }

    // Write this z-slice's partial tile
    float* Cz = g_C[blockIdx.z];
#pragma unroll
    for (int mi = 0; mi < 2; mi++) {
        int ib = i0 + wm * 32 + mi * 16 + fr;
#pragma unroll
        for (int ni = 0; ni < 4; ni++) {
            int jj = j0 + wn * 32 + ni * 8 + fk * 2;
            *(float2*)&Cz[(size_t)ib * MROWS + jj]       = make_float2(c[mi][ni][0], c[mi][ni][1]);
            *(float2*)&Cz[(size_t)(ib + 8) * MROWS + jj] = make_float2(c[mi][ni][2], c[mi][ni][3]);
        }
    }

    // Threadfence-reduction: last z-block for this tile does the loss epilogue.
    __threadfence();
    __syncthreads();
    __shared__ bool lastz;
    const int tile = blockIdx.y * (NROWS / GBM) + blockIdx.x;
    if (tid == 0) lastz = (atomicAdd(&g_tile[tile], 1u) == KSPLIT - 1);
    __syncthreads();
    if (!lastz) return;

    const int jj = tid & 63;                // tile column
    const int ih = tid >> 6;                // row half (0/1)
    const int jcol = j0 + jj;
    const float eh = g_enth[jcol];
    const int ph = g_pidhc[jcol];
    const bool jl = jcol < (2 * MROWS / 3); // 128
    float s1 = 0.f, s2 = 0.f, c1 = 0.f, c2 = 0.f;
#pragma unroll 4
    for (int u = 0; u < 32; u++) {
        int i = i0 + ih * 32 + u;
        size_t e = (size_t)i * MROWS + jcol;
        float v = 0.f;
#pragma unroll
        for (int z = 0; z < KSPLIT; z++) v += g_C[z][e];
        float d = g_entx[i] + eh - v;
        bool il = i < (2 * NROWS / 3);      // 1024
        if (g_pidi[i] == ph) {
            if (il != jl) { s1 += d; c1 += 1.f; }
        } else {
            s2 += fmaxf(MARGIN - d, 0.f);
            c2 += 1.f;
        }
    }
#pragma unroll
    for (int o = 16; o > 0; o >>= 1) {
        s1 += __shfl_xor_sync(0xffffffffu, s1, o);
        s2 += __shfl_xor_sync(0xffffffffu, s2, o);
        c1 += __shfl_xor_sync(0xffffffffu, c1, o);
        c2 += __shfl_xor_sync(0xffffffffu, c2, o);
    }
    __shared__ float red[4][4];
    __shared__ bool lastall;
    if (lane == 0) { red[wid][0] = s1; red[wid][1] = s2; red[wid][2] = c1; red[wid][3] = c2; }
    __syncthreads();
    if (tid < 4) {
        float v = red[0][tid] + red[1][tid] + red[2][tid] + red[3][tid];
        atomicAdd(&g_acc[tid], v);
    }
    __threadfence();
    if (tid == 0) lastall = (atomicAdd(&g_done, 1u) == NTILES - 1);
    __syncthreads();
    if (lastall && tid == 0) {
        volatile float* acc = g_acc;
        out[0] = acc[0] / fmaxf(acc[2], 1.f) + acc[1] / fmaxf(acc[3], 1.f);
    }
}

extern "C" void kernel_launch(void* const* d_in, const int* in_sizes, int n_in,
                              void* d_out, int out_size) {
    const float* x = (const float*)d_in[0];
    const int* pids_words = (const int*)d_in[1];   // width auto-detected on device
    (void)in_sizes; (void)n_in; (void)out_size;

    softmax_center_kernel<<<MROWS, 256>>>(x, pids_words);   // 192 blocks: 1 cluster each
    dim3 grid(NROWS / GBM, MROWS / GBN, KSPLIT);            // (24, 3, 8)
    mma_kernel<<<grid, 128>>>((float*)d_out);
}

// round 13
// speedup vs baseline: 1.1146x; 1.0443x over previous
#include <cuda_runtime.h>
#include <cstdint>

// Problem constants (fixed by setup_inputs: P=64, K=8, C=512, N=3*P*K=1536)
#define NROWS 1536
#define CDIM  512
#define MROWS 192      // 3*P
#define KINST 8        // NROWS / MROWS
#define KK    1024     // 2*CDIM  (packed [logx | xs] / [hcen | logh])
#define LOG_EPS -20.72326583694641f  // log(1e-9)
#define MARGIN 6.0f

// GEMM tiling (tf32 mma.sync m16n8k8)
#define KSPLIT 4
#define KCHUNK (KK / KSPLIT)   // 256 k per block
#define GBM 64
#define GBN 64
#define GBK 16                 // k per smem stage (2 k8 sub-steps)
#define NSTG (KCHUNK / GBK)    // 16
#define SPAD 4
#define SSTRIDE (GBK + SPAD)   // 20 words: conflict-free frag LDS, f4-aligned stores
#define NTILES ((NROWS / GBM) * (MROWS / GBN))   // 24*3 = 72

// Scratch (device globals; no allocations allowed)
__device__ float g_A[NROWS * KK];            // [logx | xs]  (tf32-rounded)
__device__ float g_B[MROWS * KK];            // [hcen | logh] (tf32-rounded)
__device__ float g_C[KSPLIT][NROWS * MROWS]; // split-K partial dot products
__device__ float g_entx[NROWS];
__device__ float g_enth[MROWS];
__device__ int   g_pidi[NROWS];
__device__ int   g_pidhc[MROWS];
__device__ float g_acc[4];                   // s1, s2, pos_cnt, neg_cnt
__device__ unsigned g_tile[NTILES];          // per-tile z-arrival counters
__device__ unsigned g_done;                  // finished-tile counter

__device__ __forceinline__ float to_tf32(float x) {
    uint32_t r;
    asm("cvt.rna.tf32.f32 %0, %1;" : "=r"(r) : "f"(x));
    return __uint_as_float(r);
}

// ---------------------------------------------------------------------------
// Kernel 1 (fused): softmax + cluster centers.
// Block b (256 thr, 8 warps) owns rows [8b, 8b+8) == exactly cluster b.
// Block 0 additionally: zero accumulators/counters, detect pids element width
// (int32 vs int64), extract per-row / per-cluster pids.
// ---------------------------------------------------------------------------
__global__ __launch_bounds__(256) void softmax_center_kernel(const float* __restrict__ x,
                                                             const int* __restrict__ pw) {
    __shared__ float sxs[KINST * CDIM];       // 16 KB staged xs
    __shared__ float sred[256];
    int tid = threadIdx.x;
    if (blockIdx.x == 0) {
        if (tid < 4) g_acc[tid] = 0.0f;
        if (tid == 0) g_done = 0u;
        if (tid < NTILES) g_tile[tid] = 0u;
        int q = 1 + 2 * tid;               // odd words 1..511 (safe for both widths)
        int nz = (pw[q] != 0) ? 1 : 0;
        int any = __syncthreads_or(nz);    // int64 LE small values -> odd words all 0
        int stride = any ? 1 : 2;
        for (int i = tid; i < NROWS; i += 256) g_pidi[i]  = pw[i * stride];
        for (int j = tid; j < MROWS; j += 256) g_pidhc[j] = pw[j * KINST * stride];
    }

    const int warp = tid >> 5;
    const int lane = tid & 31;
    const int row = blockIdx.x * KINST + warp;
    const float4* xr4 = (const float4*)(x + (size_t)row * CDIM);

    float4 v4[4];
    float mx = -1e30f;
#pragma unroll
    for (int q = 0; q < 4; q++) {
        v4[q] = xr4[lane + 32 * q];
        mx = fmaxf(mx, fmaxf(fmaxf(v4[q].x, v4[q].y), fmaxf(v4[q].z, v4[q].w)));
    }
#pragma unroll
    for (int o = 16; o > 0; o >>= 1) mx = fmaxf(mx, __shfl_xor_sync(0xffffffffu, mx, o));

    float e[16];
    float s = 0.f;
#pragma unroll
    for (int q = 0; q < 4; q++) {
        const float* vv = (const float*)&v4[q];
#pragma unroll
        for (int u = 0; u < 4; u++) { e[q * 4 + u] = __expf(vv[u] - mx); s += e[q * 4 + u]; }
    }
#pragma unroll
    for (int o = 16; o > 0; o >>= 1) s += __shfl_xor_sync(0xffffffffu, s, o);
    float ls = __logf(s);
    float inv = 1.0f / s;
    float ent = 0.f;

    float4* Ar4  = (float4*)(g_A + (size_t)row * KK);          // logx at [0,512)
    float4* Axs4 = Ar4 + CDIM / 4;                             // xs   at [512,1024)
    float4* sw4  = (float4*)(sxs + warp * CDIM);
#pragma unroll
    for (int q = 0; q < 4; q++) {
        const float* vv = (const float*)&v4[q];
        float4 lx4, xs4;
        float* lxp = (float*)&lx4; float* xsp = (float*)&xs4;
#pragma unroll
        for (int u = 0; u < 4; u++) {
            float lx = fmaxf(vv[u] - mx - ls, LOG_EPS);
            float xs = e[q * 4 + u] * inv;
            lxp[u] = to_tf32(lx);
            xsp[u] = to_tf32(xs);
            ent += xs * lx;
        }
        Ar4[lane + 32 * q]  = lx4;
        Axs4[lane + 32 * q] = xs4;
        sw4[lane + 32 * q]  = xs4;          // stage xs for the center pass
    }
#pragma unroll
    for (int o = 16; o > 0; o >>= 1) ent += __shfl_xor_sync(0xffffffffu, ent, o);
    if (lane == 0) g_entx[row] = ent;
    __syncthreads();

    // Center pass: this block IS cluster j = blockIdx.x. 2 columns per thread.
    const int j = blockIdx.x;
    float* Bj = g_B + (size_t)j * KK;
    float entp = 0.f;
#pragma unroll
    for (int t = 0; t < 2; t++) {
        int c = tid + t * 256;
        float hsum = 0.f;
#pragma unroll
        for (int r = 0; r < KINST; r++) hsum += sxs[r * CDIM + c];
        float h = hsum * (1.0f / KINST);
        float lh = __logf(fmaxf(h, 1e-9f));
        Bj[c]        = to_tf32(h);
        Bj[CDIM + c] = to_tf32(lh);
        entp += h * lh;
    }
    sred[tid] = entp;
    __syncthreads();
    for (int o = 128; o > 0; o >>= 1) {
        if (tid < o) sred[tid] += sred[tid + o];
        __syncthreads();
    }
    if (tid == 0) g_enth[j] = sred[0];
}

// ---------------------------------------------------------------------------
// Kernel 2: tf32 tensor-core GEMM, split-K=4, with fused loss epilogue.
// 128 threads = 4 warps (2x2), warp tile 32x32 = 2x4 m16n8k8 mma tiles.
// Grid (24,3,4) = 288 blocks. Last z-block per tile sums the 4 partials,
// applies the masked hinge/positive loss, atomically accumulates; last tile
// writes the scalar out.
// ---------------------------------------------------------------------------
__global__ __launch_bounds__(128, 4) void mma_kernel(float* __restrict__ out) {
    __shared__ float As[2][GBM][SSTRIDE];
    __shared__ float Bs[2][GBN][SSTRIDE];
    const int tid = threadIdx.x;
    const int lane = tid & 31;
    const int wid = tid >> 5;
    const int wm = wid & 1, wn = wid >> 1;
    const int i0 = blockIdx.x * GBM;
    const int j0 = blockIdx.y * GBN;
    const float* Ag = g_A + (size_t)i0 * KK + blockIdx.z * KCHUNK;
    const float* Bg = g_B + (size_t)j0 * KK + blockIdx.z * KCHUNK;

    const int lrow0 = tid >> 2;             // 0..31
    const int lrow1 = lrow0 + 32;           // 32..63
    const int lkc   = (tid & 3) * 4;        // 0,4,8,12

    float c[2][4][4] = {};
    float4 va0, va1, vb0, vb1;

    va0 = *(const float4*)(Ag + (size_t)lrow0 * KK + lkc);
    va1 = *(const float4*)(Ag + (size_t)lrow1 * KK + lkc);
    vb0 = *(const float4*)(Bg + (size_t)lrow0 * KK + lkc);
    vb1 = *(const float4*)(Bg + (size_t)lrow1 * KK + lkc);
    *(float4*)&As[0][lrow0][lkc] = va0;
    *(float4*)&As[0][lrow1][lkc] = va1;
    *(float4*)&Bs[0][lrow0][lkc] = vb0;
    *(float4*)&Bs[0][lrow1][lkc] = vb1;
    __syncthreads();

    const int fr = lane >> 2;   // fragment row/col
    const int fk = lane & 3;    // fragment k

    for (int st = 0; st < NSTG; st++) {
        const int buf = st & 1;
        if (st + 1 < NSTG) {
            int ck = (st + 1) * GBK;
            va0 = *(const float4*)(Ag + (size_t)lrow0 * KK + lkc + ck);
            va1 = *(const float4*)(Ag + (size_t)lrow1 * KK + lkc + ck);
            vb0 = *(const float4*)(Bg + (size_t)lrow0 * KK + lkc + ck);
            vb1 = *(const float4*)(Bg + (size_t)lrow1 * KK + lkc + ck);
        }
#pragma unroll
        for (int ks = 0; ks < 2; ks++) {
            const int k0 = ks * 8 + fk;
            uint32_t a[2][4], b[4][2];
#pragma unroll
            for (int mi = 0; mi < 2; mi++) {
                int r0 = wm * 32 + mi * 16 + fr;
                a[mi][0] = __float_as_uint(As[buf][r0][k0]);
                a[mi][1] = __float_as_uint(As[buf][r0 + 8][k0]);
                a[mi][2] = __float_as_uint(As[buf][r0][k0 + 4]);
                a[mi][3] = __float_as_uint(As[buf][r0 + 8][k0 + 4]);
            }
#pragma unroll
            for (int ni = 0; ni < 4; ni++) {
                int c0 = wn * 32 + ni * 8 + fr;
                b[ni][0] = __float_as_uint(Bs[buf][c0][k0]);
                b[ni][1] = __float_as_uint(Bs[buf][c0][k0 + 4]);
            }
#pragma unroll
            for (int mi = 0; mi < 2; mi++)
#pragma unroll
                for (int ni = 0; ni < 4; ni++)
                    asm volatile(
                        "mma.sync.aligned.m16n8k8.row.col.f32.tf32.tf32.f32 "
                        "{%0,%1,%2,%3}, {%4,%5,%6,%7}, {%8,%9}, {%0,%1,%2,%3};\n"
                        : "+f"(c[mi][ni][0]), "+f"(c[mi][ni][1]),
                          "+f"(c[mi][ni][2]), "+f"(c[mi][ni][3])
                        : "r"(a[mi][0]), "r"(a[mi][1]), "r"(a[mi][2]), "r"(a[mi][3]),
                          "r"(b[ni][0]), "r"(b[ni][1]));
        }
        if (st + 1 < NSTG) {
            __syncthreads();
            const int nb = buf ^ 1;
            *(float4*)&As[nb][lrow0][lkc] = va0;
            *(float4*)&As[nb][lrow1][lkc] = va1;
            *(float4*)&Bs[nb][lrow0][lkc] = vb0;
            *(float4*)&Bs[nb][lrow1][lkc] = vb1;
            __syncthreads();
        }
    }

    // Write this z-slice's partial tile
    float* Cz = g_C[blockIdx.z];
#pragma unroll
    for (int mi = 0; mi < 2; mi++) {
        int ib = i0 + wm * 32 + mi * 16 + fr;
#pragma unroll
        for (int ni = 0; ni < 4; ni++) {
            int jj = j0 + wn * 32 + ni * 8 + fk * 2;
            *(float2*)&Cz[(size_t)ib * MROWS + jj]       = make_float2(c[mi][ni][0], c[mi][ni][1]);
            *(float2*)&Cz[(size_t)(ib + 8) * MROWS + jj] = make_float2(c[mi][ni][2], c[mi][ni][3]);
        }
    }

    // Threadfence-reduction: last z-block for this tile does the loss epilogue.
    __threadfence();
    __syncthreads();
    __shared__ bool lastz;
    const int tile = blockIdx.y * (NROWS / GBM) + blockIdx.x;
    if (tid == 0) lastz = (atomicAdd(&g_tile[tile], 1u) == KSPLIT - 1);
    __syncthreads();
    if (!lastz) return;

    const int jj = tid & 63;                // tile column
    const int ih = tid >> 6;                // row half (0/1)
    const int jcol = j0 + jj;
    const float eh = g_enth[jcol];
    const int ph = g_pidhc[jcol];
    const bool jl = jcol < (2 * MROWS / 3); // 128
    float s1 = 0.f, s2 = 0.f, c1 = 0.f, c2 = 0.f;
#pragma unroll 8
    for (int u = 0; u < 32; u++) {
        int i = i0 + ih * 32 + u;
        size_t e = (size_t)i * MROWS + jcol;
        float v = 0.f;
#pragma unroll
        for (int z = 0; z < KSPLIT; z++) v += g_C[z][e];
        float d = g_entx[i] + eh - v;
        bool il = i < (2 * NROWS / 3);      // 1024
        if (g_pidi[i] == ph) {
            if (il != jl) { s1 += d; c1 += 1.f; }
        } else {
            s2 += fmaxf(MARGIN - d, 0.f);
            c2 += 1.f;
        }
    }
#pragma unroll
    for (int o = 16; o > 0; o >>= 1) {
        s1 += __shfl_xor_sync(0xffffffffu, s1, o);
        s2 += __shfl_xor_sync(0xffffffffu, s2, o);
        c1 += __shfl_xor_sync(0xffffffffu, c1, o);
        c2 += __shfl_xor_sync(0xffffffffu, c2, o);
    }
    __shared__ float red[4][4];
    __shared__ bool lastall;
    if (lane == 0) { red[wid][0] = s1; red[wid][1] = s2; red[wid][2] = c1; red[wid][3] = c2; }
    __syncthreads();
    if (tid < 4) {
        float v = red[0][tid] + red[1][tid] + red[2][tid] + red[3][tid];
        atomicAdd(&g_acc[tid], v);
    }
    __threadfence();
    if (tid == 0) lastall = (atomicAdd(&g_done, 1u) == NTILES - 1);
    __syncthreads();
    if (lastall && tid == 0) {
        volatile float* acc = g_acc;
        out[0] = acc[0] / fmaxf(acc[2], 1.f) + acc[1] / fmaxf(acc[3], 1.f);
    }
}

extern "C" void kernel_launch(void* const* d_in, const int* in_sizes, int n_in,
                              void* d_out, int out_size) {
    const float* x = (const float*)d_in[0];
    const int* pids_words = (const int*)d_in[1];   // width auto-detected on device
    (void)in_sizes; (void)n_in; (void)out_size;

    softmax_center_kernel<<<MROWS, 256>>>(x, pids_words);   // 192 blocks: 1 cluster each
    dim3 grid(NROWS / GBM, MROWS / GBN, KSPLIT);            // (24, 3, 4)
    mma_kernel<<<grid, 128>>>((float*)d_out);
}